// round 3
// baseline (speedup 1.0000x reference)
#include <cuda_runtime.h>
#include <math.h>

#define DMODEL 1024
#define DFF    4096
#define NHEADS 16
#define DKV    64
#define BATCH  8
#define SEQ    1024
#define MROWS  (BATCH*SEQ)    // 8192
#define BH     (BATCH*NHEADS) // 128

// ---------------- scratch (no allocations allowed) ----------------
__device__ float g_q[BH*SEQ*DKV];       // [B,H,S,Dk]
__device__ float g_k[BH*SEQ*DKV];
__device__ float g_v[BH*SEQ*DKV];
__device__ float g_ctx[MROWS*DMODEL];   // [B,S,H*Dv]
__device__ float g_tmp[MROWS*DMODEL];   // pre-LN buffer
__device__ float g_ao[MROWS*DMODEL];    // attn_out (post LN1)
__device__ float g_h[(size_t)MROWS*DFF];// FFN hidden

// ---------------- helpers ----------------
__device__ __forceinline__ unsigned f2tf(float x) {
    unsigned u;
    asm("cvt.rna.tf32.f32 %0, %1;" : "=r"(u) : "f"(x));
    return u;
}

__device__ __forceinline__ void mma_tf32(float* c, const unsigned* a, const unsigned* b) {
    asm volatile(
        "mma.sync.aligned.m16n8k8.row.col.f32.tf32.tf32.f32 "
        "{%0,%1,%2,%3},{%4,%5,%6,%7},{%8,%9},{%0,%1,%2,%3};"
        : "+f"(c[0]), "+f"(c[1]), "+f"(c[2]), "+f"(c[3])
        : "r"(a[0]), "r"(a[1]), "r"(a[2]), "r"(a[3]), "r"(b[0]), "r"(b[1]));
}

__device__ __forceinline__ unsigned sptr(const void* p) {
    return (unsigned)__cvta_generic_to_shared(p);
}
#define CP_ASYNC16(dst, src) \
    asm volatile("cp.async.cg.shared.global [%0], [%1], 16;" :: "r"(dst), "l"(src))
#define CP_COMMIT() asm volatile("cp.async.commit_group;")
#define CP_WAIT(n)  asm volatile("cp.async.wait_group %0;" :: "n"(n))

// =====================================================================
// Big pipelined GEMM: block 128x256, kchunk 16, 3-stage cp.async,
// 8 warps (2Mx4N), warp tile 64x64 (4x8 m16n8k8 tf32 atoms).
// fp32 data fed raw to tf32 mma (HW uses top 19 bits).
// modes: 0 plain+bias? no -> 0: plain, 1 qkv-remap(+bias), 2 +bias+resid,
//        3 relu(+bias), 4 scores(scale+mask, no bias)
// =====================================================================
template<int MODE, bool TRANSB>
__global__ void __launch_bounds__(256, 1) gemm_big(
    const float* __restrict__ A, const float* __restrict__ B,
    const float* __restrict__ bias, const float* __restrict__ resid,
    const unsigned char* __restrict__ mask,
    float* __restrict__ C, int M, int N, int K,
    long long sA, long long sB, long long sC)
{
    constexpr int BM = 128, BN = 256, BK = 16, S = 3;
    constexpr int ASTR = 20;                    // A row stride (floats), 16B aligned
    constexpr int BSTR = TRANSB ? 20 : 260;     // B row stride
    constexpr int AFL  = BM * ASTR;             // 2560 floats / stage
    constexpr int BFL  = TRANSB ? BN * 20 : BK * 260;

    extern __shared__ float sm[];
    float* Asm = sm;                // [S][AFL]
    float* Bsm = sm + S * AFL;      // [S][BFL]

    const int tid = threadIdx.x;
    const int bm = blockIdx.y, bn = blockIdx.x, bz = blockIdx.z;
    A += (long long)bz * sA;
    B += (long long)bz * sB;
    C += (long long)bz * sC;

    const int lane = tid & 31, wid = tid >> 5;
    const int warpM = wid >> 2, warpN = wid & 3;
    const int g = lane >> 2, t = lane & 3;

    // ---- cp.async source/dest setup ----
    const int arow  = tid >> 1;
    const int akoff = (tid & 1) * 8;
    const float* Ag  = A + (size_t)(bm * BM + arow) * K + akoff;
    const unsigned aS0 = sptr(Asm) + (arow * ASTR + akoff) * 4;

    const float* Bg;
    unsigned bS0;
    if (TRANSB) {                       // B is [N][K]; Bs layout [n][20]
        Bg  = B + (size_t)(bn * BN + tid) * K;
        bS0 = sptr(Bsm) + (tid * BSTR) * 4;
    } else {                            // B is [K][N]; Bs layout [k][260]
        const int krow = tid >> 4, noff = (tid & 15) * 16;
        Bg  = B + (size_t)krow * N + bn * BN + noff;
        bS0 = sptr(Bsm) + (krow * BSTR + noff) * 4;
    }

    const int nch = K / BK;

    auto load_chunk = [&](int ch) {
        const int st = ch % S;
        {
            unsigned ad = aS0 + st * AFL * 4;
            const float* ap = Ag + ch * BK;
            CP_ASYNC16(ad, ap);
            CP_ASYNC16(ad + 16, ap + 4);
        }
        unsigned bd = bS0 + st * BFL * 4;
        if (TRANSB) {
            const float* bp = Bg + ch * BK;
            #pragma unroll
            for (int i = 0; i < 4; i++) CP_ASYNC16(bd + i * 16, bp + i * 4);
        } else {
            const float* bp = Bg + (size_t)ch * BK * N;
            #pragma unroll
            for (int i = 0; i < 4; i++) CP_ASYNC16(bd + i * 16, bp + i * 4);
        }
    };

    float acc[4][8][4];
    #pragma unroll
    for (int i = 0; i < 4; i++)
        #pragma unroll
        for (int j = 0; j < 8; j++)
            #pragma unroll
            for (int r = 0; r < 4; r++) acc[i][j][r] = 0.f;

    // prologue: stages 0..S-2
    #pragma unroll
    for (int ch = 0; ch < S - 1; ch++) {
        if (ch < nch) load_chunk(ch);
        CP_COMMIT();
    }

    for (int ch = 0; ch < nch; ch++) {
        CP_WAIT(S - 2);          // chunk ch resident
        __syncthreads();         // all threads done with stage (ch)%S's previous life
        if (ch + S - 1 < nch) load_chunk(ch + S - 1);
        CP_COMMIT();

        const float* As  = Asm + (ch % S) * AFL;
        const float* Bss = Bsm + (ch % S) * BFL;

        #pragma unroll
        for (int ks = 0; ks < 2; ks++) {
            const int kk = ks * 8;
            unsigned af[4][4], bf[8][2];
            #pragma unroll
            for (int mt = 0; mt < 4; mt++) {
                const int m0 = warpM * 64 + mt * 16 + g;
                af[mt][0] = __float_as_uint(As[m0 * ASTR + kk + t]);
                af[mt][1] = __float_as_uint(As[(m0 + 8) * ASTR + kk + t]);
                af[mt][2] = __float_as_uint(As[m0 * ASTR + kk + t + 4]);
                af[mt][3] = __float_as_uint(As[(m0 + 8) * ASTR + kk + t + 4]);
            }
            #pragma unroll
            for (int nt = 0; nt < 8; nt++) {
                const int n0 = warpN * 64 + nt * 8 + g;
                if (TRANSB) {
                    bf[nt][0] = __float_as_uint(Bss[n0 * 20 + kk + t]);
                    bf[nt][1] = __float_as_uint(Bss[n0 * 20 + kk + t + 4]);
                } else {
                    bf[nt][0] = __float_as_uint(Bss[(kk + t) * 260 + n0]);
                    bf[nt][1] = __float_as_uint(Bss[(kk + t + 4) * 260 + n0]);
                }
            }
            #pragma unroll
            for (int mt = 0; mt < 4; mt++)
                #pragma unroll
                for (int nt = 0; nt < 8; nt++)
                    mma_tf32(acc[mt][nt], af[mt], bf[nt]);
        }
        // no trailing sync needed: next iteration's barrier (after CP_WAIT)
        // precedes any overwrite of this stage.
        __syncthreads();
    }

    // ---- epilogue ----
    #pragma unroll
    for (int mt = 0; mt < 4; mt++) {
        const int r0 = bm * BM + warpM * 64 + mt * 16 + g;
        const int r1 = r0 + 8;
        #pragma unroll
        for (int nt = 0; nt < 8; nt++) {
            const int c = bn * BN + warpN * 64 + nt * 8 + 2 * t;
            float2 lo = make_float2(acc[mt][nt][0], acc[mt][nt][1]);  // row r0
            float2 hi = make_float2(acc[mt][nt][2], acc[mt][nt][3]);  // row r1

            if (MODE == 1 || MODE == 2 || MODE == 3) {
                const float2 bv = *(const float2*)(bias + c);
                lo.x += bv.x; lo.y += bv.y; hi.x += bv.x; hi.y += bv.y;
            }
            if (MODE == 2) {
                const float2 q0 = *(const float2*)(resid + (size_t)r0 * N + c);
                const float2 q1 = *(const float2*)(resid + (size_t)r1 * N + c);
                lo.x += q0.x; lo.y += q0.y; hi.x += q1.x; hi.y += q1.y;
            }
            if (MODE == 3) {
                lo.x = fmaxf(lo.x, 0.f); lo.y = fmaxf(lo.y, 0.f);
                hi.x = fmaxf(hi.x, 0.f); hi.y = fmaxf(hi.y, 0.f);
            }

            if (MODE == 1) {
                const int h = c >> 6, d = c & 63;
                const int bb0 = r0 >> 10, s0 = r0 & 1023;
                const int bb1 = r1 >> 10, s1 = r1 & 1023;
                *(float2*)(C + (((size_t)(bb0*NHEADS + h))*SEQ + s0)*DKV + d) = lo;
                *(float2*)(C + (((size_t)(bb1*NHEADS + h))*SEQ + s1)*DKV + d) = hi;
            } else if (MODE == 4) {
                const unsigned char* mb = mask + (size_t)(bz >> 4) * SEQ * SEQ;
                lo.x *= 0.125f; lo.y *= 0.125f; hi.x *= 0.125f; hi.y *= 0.125f;
                if (mb[(size_t)r0*SEQ + c])     lo.x = -1e9f;
                if (mb[(size_t)r0*SEQ + c + 1]) lo.y = -1e9f;
                if (mb[(size_t)r1*SEQ + c])     hi.x = -1e9f;
                if (mb[(size_t)r1*SEQ + c + 1]) hi.y = -1e9f;
                *(float2*)(C + (size_t)r0 * N + c) = lo;
                *(float2*)(C + (size_t)r1 * N + c) = hi;
            } else {
                *(float2*)(C + (size_t)r0 * N + c) = lo;
                *(float2*)(C + (size_t)r1 * N + c) = hi;
            }
        }
    }
}

// =====================================================================
// Old register-staged kernel, kept only for ctx (N=64): block 128x64
// =====================================================================
template<int BN, int MODE, bool TRANSB>
__global__ void __launch_bounds__(256, 2) gemm_tc(
    const float* __restrict__ A, const float* __restrict__ B,
    const float* __restrict__ bias, const float* __restrict__ resid,
    const unsigned char* __restrict__ mask,
    float* __restrict__ C, int M, int N, int K,
    long long sA, long long sB, long long sC)
{
    constexpr int NT = BN / 32;
    constexpr int WN = BN / 4;
    __shared__ unsigned As[2][16][132];
    __shared__ unsigned Bs[2][16][BN + 4];

    const int tid = threadIdx.x;
    const int bm = blockIdx.y, bn = blockIdx.x, bz = blockIdx.z;
    A += (long long)bz * sA;
    B += (long long)bz * sB;
    C += (long long)bz * sC;

    const int lane = tid & 31, wid = tid >> 5;
    const int warpM = wid >> 2, warpN = wid & 3;
    const int g = lane >> 2, t = lane & 3;

    const float* Abase = A + (size_t)(bm * 128 + (tid >> 1)) * K + ((tid & 1) * 8);
    const float* Bbase = B + (size_t)(tid >> 4) * N + bn * 64 + ((tid & 15) * 4);

    float fa[8], fb[4];
    float acc[4][NT][4];
    #pragma unroll
    for (int i = 0; i < 4; i++)
        #pragma unroll
        for (int j = 0; j < NT; j++)
            #pragma unroll
            for (int r = 0; r < 4; r++) acc[i][j][r] = 0.f;

    const int nch = K >> 4;
    {
        const float* p = Abase;
        float4 u = *(const float4*)p, v = *(const float4*)(p + 4);
        fa[0]=u.x; fa[1]=u.y; fa[2]=u.z; fa[3]=u.w;
        fa[4]=v.x; fa[5]=v.y; fa[6]=v.z; fa[7]=v.w;
        float4 a = *(const float4*)Bbase;
        fb[0]=a.x; fb[1]=a.y; fb[2]=a.z; fb[3]=a.w;
    }
    {
        const int r = tid >> 1, c0 = (tid & 1) * 8;
        #pragma unroll
        for (int c = 0; c < 8; c++) As[0][c0 + c][r] = f2tf(fa[c]);
        const int br = tid >> 4, bc0 = (tid & 15) * 4;
        #pragma unroll
        for (int c = 0; c < 4; c++) Bs[0][br][bc0 + c] = f2tf(fb[c]);
    }
    __syncthreads();

    for (int ch = 0; ch < nch; ch++) {
        const int cur = ch & 1, nxt = cur ^ 1;
        const bool more = (ch + 1 < nch);
        if (more) {
            const float* p = Abase + (ch + 1) * 16;
            float4 u = *(const float4*)p, v = *(const float4*)(p + 4);
            fa[0]=u.x; fa[1]=u.y; fa[2]=u.z; fa[3]=u.w;
            fa[4]=v.x; fa[5]=v.y; fa[6]=v.z; fa[7]=v.w;
            const float* q = Bbase + (size_t)(ch + 1) * 16 * N;
            float4 a = *(const float4*)q;
            fb[0]=a.x; fb[1]=a.y; fb[2]=a.z; fb[3]=a.w;
        }
        #pragma unroll
        for (int ks = 0; ks < 2; ks++) {
            const int kk = ks * 8;
            unsigned af[4][4], bf[NT][2];
            #pragma unroll
            for (int mt = 0; mt < 4; mt++) {
                const int mb = warpM * 64 + mt * 16 + g;
                af[mt][0] = As[cur][kk + t][mb];
                af[mt][1] = As[cur][kk + t][mb + 8];
                af[mt][2] = As[cur][kk + t + 4][mb];
                af[mt][3] = As[cur][kk + t + 4][mb + 8];
            }
            #pragma unroll
            for (int nt = 0; nt < NT; nt++) {
                const int nb = warpN * WN + nt * 8 + g;
                bf[nt][0] = Bs[cur][kk + t][nb];
                bf[nt][1] = Bs[cur][kk + t + 4][nb];
            }
            #pragma unroll
            for (int mt = 0; mt < 4; mt++)
                #pragma unroll
                for (int nt = 0; nt < NT; nt++)
                    mma_tf32(acc[mt][nt], af[mt], bf[nt]);
        }
        if (more) {
            const int r = tid >> 1, c0 = (tid & 1) * 8;
            #pragma unroll
            for (int c = 0; c < 8; c++) As[nxt][c0 + c][r] = f2tf(fa[c]);
            const int br = tid >> 4, bc0 = (tid & 15) * 4;
            #pragma unroll
            for (int c = 0; c < 4; c++) Bs[nxt][br][bc0 + c] = f2tf(fb[c]);
        }
        __syncthreads();
    }

    #pragma unroll
    for (int mt = 0; mt < 4; mt++) {
        const int r0 = bm * 128 + warpM * 64 + mt * 16 + g;
        const int r1 = r0 + 8;
        #pragma unroll
        for (int nt = 0; nt < NT; nt++) {
            const int c = bn * BN + warpN * WN + nt * 8 + 2 * t;
            float2 lo = make_float2(acc[mt][nt][0], acc[mt][nt][1]);
            float2 hi = make_float2(acc[mt][nt][2], acc[mt][nt][3]);
            // MODE 5 only: ctx remap [B,S,H*Dv]
            const int b = bz >> 4, h = bz & 15;
            *(float2*)(C + ((size_t)b*SEQ + r0)*DMODEL + h*DKV + c) = lo;
            *(float2*)(C + ((size_t)b*SEQ + r1)*DMODEL + h*DKV + c) = hi;
        }
    }
}

// ---------------- row softmax over 1024, in place ----------------
__global__ __launch_bounds__(256) void softmax_rows(float* __restrict__ attn)
{
    __shared__ float sbuf[256];
    const size_t row = blockIdx.x;
    float* p = attn + row * 1024;
    const int tid = threadIdx.x;
    float4 v = *(const float4*)(p + tid*4);
    float m = fmaxf(fmaxf(v.x, v.y), fmaxf(v.z, v.w));
    sbuf[tid] = m; __syncthreads();
    for (int s = 128; s > 0; s >>= 1) {
        if (tid < s) sbuf[tid] = fmaxf(sbuf[tid], sbuf[tid+s]);
        __syncthreads();
    }
    m = sbuf[0]; __syncthreads();
    v.x = __expf(v.x - m); v.y = __expf(v.y - m);
    v.z = __expf(v.z - m); v.w = __expf(v.w - m);
    sbuf[tid] = v.x + v.y + v.z + v.w; __syncthreads();
    for (int s = 128; s > 0; s >>= 1) {
        if (tid < s) sbuf[tid] += sbuf[tid+s];
        __syncthreads();
    }
    const float inv = 1.f / sbuf[0];
    v.x *= inv; v.y *= inv; v.z *= inv; v.w *= inv;
    *(float4*)(p + tid*4) = v;
}

// ---------------- layernorm over last dim 1024 ----------------
__global__ __launch_bounds__(256) void layernorm_rows(
    const float* __restrict__ in, const float* __restrict__ g,
    const float* __restrict__ bta, float* __restrict__ out)
{
    __shared__ float s1[256], s2[256];
    const size_t row = blockIdx.x;
    const float* p = in + row * DMODEL;
    const int tid = threadIdx.x;
    float4 v = *(const float4*)(p + tid*4);
    s1[tid] = v.x + v.y + v.z + v.w;
    s2[tid] = v.x*v.x + v.y*v.y + v.z*v.z + v.w*v.w;
    __syncthreads();
    for (int st = 128; st > 0; st >>= 1) {
        if (tid < st) { s1[tid] += s1[tid+st]; s2[tid] += s2[tid+st]; }
        __syncthreads();
    }
    const float mu  = s1[0] * (1.f/DMODEL);
    const float var = s2[0] * (1.f/DMODEL) - mu*mu;
    const float rs  = rsqrtf(var + 1e-5f);
    float4 gv = *(const float4*)(g + tid*4);
    float4 bv = *(const float4*)(bta + tid*4);
    float4 o;
    o.x = (v.x - mu)*rs*gv.x + bv.x;
    o.y = (v.y - mu)*rs*gv.y + bv.y;
    o.z = (v.z - mu)*rs*gv.z + bv.z;
    o.w = (v.w - mu)*rs*gv.w + bv.w;
    *(float4*)(out + row*DMODEL + tid*4) = o;
}

// ---------------- launch ----------------
extern "C" void kernel_launch(void* const* d_in, const int* in_sizes, int n_in,
                              void* d_out, int out_size)
{
    const float* x    = (const float*)d_in[0];
    const unsigned char* mask = (const unsigned char*)d_in[1];
    const float* Wq = (const float*)d_in[2];  const float* bq = (const float*)d_in[3];
    const float* Wk = (const float*)d_in[4];  const float* bk = (const float*)d_in[5];
    const float* Wv = (const float*)d_in[6];  const float* bv = (const float*)d_in[7];
    const float* Wo = (const float*)d_in[8];  const float* bo = (const float*)d_in[9];
    const float* ln1g = (const float*)d_in[10]; const float* ln1b = (const float*)d_in[11];
    const float* W1 = (const float*)d_in[12]; const float* b1 = (const float*)d_in[13];
    const float* W2 = (const float*)d_in[14]; const float* b2 = (const float*)d_in[15];
    const float* ln2g = (const float*)d_in[16]; const float* ln2b = (const float*)d_in[17];

    float* out = (float*)d_out;
    float* ffn_out = out;                                    // [B,S,D]
    float* attn    = out + (size_t)MROWS * DMODEL;           // [B,H,S,S]

    float *qp, *kp, *vp, *ctxp, *tmpp, *aop, *hp;
    cudaGetSymbolAddress((void**)&qp,   g_q);
    cudaGetSymbolAddress((void**)&kp,   g_k);
    cudaGetSymbolAddress((void**)&vp,   g_v);
    cudaGetSymbolAddress((void**)&ctxp, g_ctx);
    cudaGetSymbolAddress((void**)&tmpp, g_tmp);
    cudaGetSymbolAddress((void**)&aop,  g_ao);
    cudaGetSymbolAddress((void**)&hp,   g_h);

    // dynamic smem sizes
    const int SM_DENSE = 3 * (128*20 + 16*260) * 4;   // 80640 B
    const int SM_TRANS = 3 * (128*20 + 256*20) * 4;   // 92160 B
    cudaFuncSetAttribute(gemm_big<1,false>, cudaFuncAttributeMaxDynamicSharedMemorySize, SM_DENSE);
    cudaFuncSetAttribute(gemm_big<2,false>, cudaFuncAttributeMaxDynamicSharedMemorySize, SM_DENSE);
    cudaFuncSetAttribute(gemm_big<3,false>, cudaFuncAttributeMaxDynamicSharedMemorySize, SM_DENSE);
    cudaFuncSetAttribute(gemm_big<4,true>,  cudaFuncAttributeMaxDynamicSharedMemorySize, SM_TRANS);

    // QKV projections -> [B,H,S,Dk]
    gemm_big<1,false><<<dim3(4,64,1),256,SM_DENSE>>>(x, Wq, bq, nullptr, nullptr, qp, MROWS, DMODEL, DMODEL, 0,0,0);
    gemm_big<1,false><<<dim3(4,64,1),256,SM_DENSE>>>(x, Wk, bk, nullptr, nullptr, kp, MROWS, DMODEL, DMODEL, 0,0,0);
    gemm_big<1,false><<<dim3(4,64,1),256,SM_DENSE>>>(x, Wv, bv, nullptr, nullptr, vp, MROWS, DMODEL, DMODEL, 0,0,0);

    // scores: q @ k^T * 0.125 + mask -> attn, then softmax in place
    gemm_big<4,true><<<dim3(4,8,BH),256,SM_TRANS>>>(qp, kp, nullptr, nullptr, mask, attn,
                                                    SEQ, SEQ, DKV,
                                                    (long long)SEQ*DKV, (long long)SEQ*DKV, (long long)SEQ*SEQ);
    softmax_rows<<<BH * SEQ, 256>>>(attn);

    // ctx = attn @ v -> [B,S,H*Dv]
    gemm_tc<64,5,false><<<dim3(1,8,BH),256>>>(attn, vp, nullptr, nullptr, nullptr, ctxp,
                                              SEQ, DKV, SEQ,
                                              (long long)SEQ*SEQ, (long long)SEQ*DKV, 0);

    // out proj + residual, LN1
    gemm_big<2,false><<<dim3(4,64,1),256,SM_DENSE>>>(ctxp, Wo, bo, x, nullptr, tmpp, MROWS, DMODEL, DMODEL, 0,0,0);
    layernorm_rows<<<MROWS, 256>>>(tmpp, ln1g, ln1b, aop);

    // FFN
    gemm_big<3,false><<<dim3(16,64,1),256,SM_DENSE>>>(aop, W1, b1, nullptr, nullptr, hp, MROWS, DFF, DMODEL, 0,0,0);
    gemm_big<2,false><<<dim3(4,64,1),256,SM_DENSE>>>(hp, W2, b2, aop, nullptr, tmpp, MROWS, DMODEL, DFF, 0,0,0);
    layernorm_rows<<<MROWS, 256>>>(tmpp, ln2g, ln2b, ffn_out);
}

// round 4
// speedup vs baseline: 1.5933x; 1.5933x over previous
#include <cuda_runtime.h>
#include <math.h>

#define DMODEL 1024
#define DFF    4096
#define NHEADS 16
#define DKV    64
#define BATCH  8
#define SEQ    1024
#define MROWS  (BATCH*SEQ)    // 8192
#define BH     (BATCH*NHEADS) // 128

// ---------------- scratch (no allocations allowed) ----------------
__device__ float g_q[BH*SEQ*DKV];       // [B,H,S,Dk]
__device__ float g_k[BH*SEQ*DKV];
__device__ float g_v[BH*SEQ*DKV];
__device__ float g_ctx[MROWS*DMODEL];   // [B,S,H*Dv]
__device__ float g_tmp[MROWS*DMODEL];   // pre-LN buffer
__device__ float g_ao[MROWS*DMODEL];    // attn_out (post LN1)
__device__ float g_h[(size_t)MROWS*DFF];// FFN hidden

// ---------------- helpers ----------------
__device__ __forceinline__ unsigned f2tf(float x) {
    unsigned u;
    asm("cvt.rna.tf32.f32 %0, %1;" : "=r"(u) : "f"(x));
    return u;
}

__device__ __forceinline__ void mma_tf32(float* c, const unsigned* a, const unsigned* b) {
    asm volatile(
        "mma.sync.aligned.m16n8k8.row.col.f32.tf32.tf32.f32 "
        "{%0,%1,%2,%3},{%4,%5,%6,%7},{%8,%9},{%0,%1,%2,%3};"
        : "+f"(c[0]), "+f"(c[1]), "+f"(c[2]), "+f"(c[3])
        : "r"(a[0]), "r"(a[1]), "r"(a[2]), "r"(a[3]), "r"(b[0]), "r"(b[1]));
}

// A fragment smem offset (bytes within one A stage, 8192 B).
// Layout: [mtile(8)][ks(2)][lane(32)][slot(4 words)] with XOR swizzle of
// bits[6:4] by bits[9:7] (= ks | lane>>3) -> staging ~2-way, consumer LDS.128
// conflict-free.
__device__ __forceinline__ unsigned a_off(int mtks, int lane, int slot) {
    unsigned b = ((unsigned)mtks << 9) + (lane << 4) + (slot << 2);
    return b ^ ((b >> 3) & 0x70);
}
// B fragment smem offset (bytes within one B stage, BN*64 B).
// Layout: [ntile][ks][lane(32)][lohi(2 words)], XOR bits[6:4] by ntile[2:0]
// (bits[11:9]) and bit4 by ks (bit8) -> consumer LDS.64 conflict-free.
__device__ __forceinline__ unsigned b_off(int ntks, int lane, int lohi) {
    unsigned b = ((unsigned)ntks << 8) + (lane << 3) + (lohi << 2);
    return b ^ ((b >> 5) & 0x70) ^ ((b >> 4) & 0x10);
}

// =====================================================================
// Tensor-core GEMM, fragment-major swizzled smem.
// Block 128 x BN x 16, 8 warps (2M x 4N), warp tile 64 x (BN/4).
// modes: 1 qkv-remap(+bias), 2 +bias+resid, 3 relu(+bias),
//        4 scores(scale+mask), 5 ctx-remap
// =====================================================================
template<int BN, int MODE, bool TRANSB>
__global__ void __launch_bounds__(256, 2) gemm_tc2(
    const float* __restrict__ A, const float* __restrict__ B,
    const float* __restrict__ bias, const float* __restrict__ resid,
    const unsigned char* __restrict__ mask,
    float* __restrict__ C, int M, int N, int K,
    long long sA, long long sB, long long sC)
{
    constexpr int NT  = BN / 32;      // n atoms per warp
    constexpr int BPC = BN / 16;      // dense-B floats per thread per chunk
    constexpr int AW  = 2048;         // words per A stage
    constexpr int BW  = BN * 16;      // words per B stage

    __shared__ __align__(16) unsigned Asm[2][AW];
    __shared__ __align__(16) unsigned Bsm[2][BW];

    const int tid = threadIdx.x;
    const int bm = blockIdx.y, bn = blockIdx.x, bz = blockIdx.z;
    A += (long long)bz * sA;
    B += (long long)bz * sB;
    C += (long long)bz * sC;

    const int lane = tid & 31, wid = tid >> 5;
    const int warpM = wid >> 2, warpN = wid & 3;
    const int g = lane >> 2, t = lane & 3;

    // ---- staging thread roles ----
    const int arow = tid >> 1;               // 0..127
    const int aks  = tid & 1;                // k-octet
    const float* Ag = A + (size_t)(bm * 128 + arow) * K + aks * 8;
    const int amtile = arow >> 4, ag = arow & 7, ahi = (arow >> 3) & 1;

    const float* Bg;
    int b_nrow_ks = 0;                       // trans only
    int b_krow = 0, b_noff = 0;              // dense only
    if (TRANSB) {
        b_nrow_ks = tid & 1;
        Bg = B + (size_t)(bn * BN + (tid >> 1)) * K + (tid & 1) * 8;
    } else {
        b_krow = tid >> 4;
        b_noff = (tid & 15) * BPC;
        Bg = B + (size_t)b_krow * N + bn * BN + b_noff;
    }

    float fa[8], fb[8];
    float acc[4][NT][4];
    #pragma unroll
    for (int i = 0; i < 4; i++)
        #pragma unroll
        for (int j = 0; j < NT; j++)
            #pragma unroll
            for (int r = 0; r < 4; r++) acc[i][j][r] = 0.f;

    const int nch = K >> 4;

    // ---- load chunk into regs ----
    auto fetch = [&](int ch) {
        const float* p = Ag + ch * 16;
        float4 u = *(const float4*)p, v = *(const float4*)(p + 4);
        fa[0]=u.x; fa[1]=u.y; fa[2]=u.z; fa[3]=u.w;
        fa[4]=v.x; fa[5]=v.y; fa[6]=v.z; fa[7]=v.w;
        if (TRANSB) {
            const float* q = Bg + ch * 16;
            float4 a = *(const float4*)q, b = *(const float4*)(q + 4);
            fb[0]=a.x; fb[1]=a.y; fb[2]=a.z; fb[3]=a.w;
            fb[4]=b.x; fb[5]=b.y; fb[6]=b.z; fb[7]=b.w;
        } else {
            const float* q = Bg + (size_t)ch * 16 * N;
            float4 a = *(const float4*)q;
            fb[0]=a.x; fb[1]=a.y; fb[2]=a.z; fb[3]=a.w;
            if (BPC == 8) {
                float4 b = *(const float4*)(q + 4);
                fb[4]=b.x; fb[5]=b.y; fb[6]=b.z; fb[7]=b.w;
            }
        }
    };

    // ---- store regs into fragment-major smem (with tf32 rounding) ----
    auto store_stage = [&](int st) {
        char* Ab = (char*)Asm[st];
        #pragma unroll
        for (int c = 0; c < 8; c++) {
            const int tt = c & 3, lohi = c >> 2;
            const int sl = ahi + 2 * lohi;
            *(unsigned*)(Ab + a_off(amtile * 2 + aks, ag * 4 + tt, sl)) = f2tf(fa[c]);
        }
        char* Bb = (char*)Bsm[st];
        if (TRANSB) {
            const int nrow = tid >> 1;
            const int ntile = nrow >> 3, bg = nrow & 7;
            #pragma unroll
            for (int c = 0; c < 8; c++) {
                const int tt = c & 3, lohi = c >> 2;
                *(unsigned*)(Bb + b_off(ntile * 2 + b_nrow_ks, bg * 4 + tt, lohi)) = f2tf(fb[c]);
            }
        } else {
            const int ks = b_krow >> 3, tt = b_krow & 3, lohi = (b_krow >> 2) & 1;
            #pragma unroll
            for (int c = 0; c < BPC; c++) {
                const int n = b_noff + c;
                const int ntile = n >> 3, bg = n & 7;
                *(unsigned*)(Bb + b_off(ntile * 2 + ks, bg * 4 + tt, lohi)) = f2tf(fb[c]);
            }
        }
    };

    fetch(0);
    store_stage(0);
    __syncthreads();

    for (int ch = 0; ch < nch; ch++) {
        const int cur = ch & 1, nxt = cur ^ 1;
        const bool more = (ch + 1 < nch);
        if (more) fetch(ch + 1);

        const char* Ac = (const char*)Asm[cur];
        const char* Bc = (const char*)Bsm[cur];
        #pragma unroll
        for (int ks = 0; ks < 2; ks++) {
            unsigned af[4][4], bfr[NT][2];
            #pragma unroll
            for (int mt = 0; mt < 4; mt++) {
                uint4 v = *(const uint4*)(Ac + a_off((warpM * 4 + mt) * 2 + ks, lane, 0));
                af[mt][0] = v.x; af[mt][1] = v.y; af[mt][2] = v.z; af[mt][3] = v.w;
            }
            #pragma unroll
            for (int nt = 0; nt < NT; nt++) {
                uint2 v = *(const uint2*)(Bc + b_off((warpN * NT + nt) * 2 + ks, lane, 0));
                bfr[nt][0] = v.x; bfr[nt][1] = v.y;
            }
            #pragma unroll
            for (int mt = 0; mt < 4; mt++)
                #pragma unroll
                for (int nt = 0; nt < NT; nt++)
                    mma_tf32(acc[mt][nt], af[mt], bfr[nt]);
        }

        if (more) store_stage(nxt);
        __syncthreads();
    }

    // ---- epilogue ----
    #pragma unroll
    for (int mt = 0; mt < 4; mt++) {
        const int r0 = bm * 128 + warpM * 64 + mt * 16 + g;
        const int r1 = r0 + 8;
        #pragma unroll
        for (int nt = 0; nt < NT; nt++) {
            const int c = bn * BN + warpN * (BN / 4) + nt * 8 + 2 * t;
            float2 lo = make_float2(acc[mt][nt][0], acc[mt][nt][1]);  // row r0
            float2 hi = make_float2(acc[mt][nt][2], acc[mt][nt][3]);  // row r1

            if (MODE == 1 || MODE == 2 || MODE == 3) {
                const float2 bv = *(const float2*)(bias + c);
                lo.x += bv.x; lo.y += bv.y; hi.x += bv.x; hi.y += bv.y;
            }
            if (MODE == 2) {
                const float2 q0 = *(const float2*)(resid + (size_t)r0 * N + c);
                const float2 q1 = *(const float2*)(resid + (size_t)r1 * N + c);
                lo.x += q0.x; lo.y += q0.y; hi.x += q1.x; hi.y += q1.y;
            }
            if (MODE == 3) {
                lo.x = fmaxf(lo.x, 0.f); lo.y = fmaxf(lo.y, 0.f);
                hi.x = fmaxf(hi.x, 0.f); hi.y = fmaxf(hi.y, 0.f);
            }

            if (MODE == 1) {
                const int h = c >> 6, d = c & 63;
                const int bb0 = r0 >> 10, s0 = r0 & 1023;
                const int bb1 = r1 >> 10, s1 = r1 & 1023;
                *(float2*)(C + (((size_t)(bb0*NHEADS + h))*SEQ + s0)*DKV + d) = lo;
                *(float2*)(C + (((size_t)(bb1*NHEADS + h))*SEQ + s1)*DKV + d) = hi;
            } else if (MODE == 4) {
                const unsigned char* mb = mask + (size_t)(bz >> 4) * SEQ * SEQ;
                lo.x *= 0.125f; lo.y *= 0.125f; hi.x *= 0.125f; hi.y *= 0.125f;
                if (mb[(size_t)r0*SEQ + c])     lo.x = -1e9f;
                if (mb[(size_t)r0*SEQ + c + 1]) lo.y = -1e9f;
                if (mb[(size_t)r1*SEQ + c])     hi.x = -1e9f;
                if (mb[(size_t)r1*SEQ + c + 1]) hi.y = -1e9f;
                *(float2*)(C + (size_t)r0 * N + c) = lo;
                *(float2*)(C + (size_t)r1 * N + c) = hi;
            } else if (MODE == 5) {
                const int b = bz >> 4, h = bz & 15;
                *(float2*)(C + ((size_t)b*SEQ + r0)*DMODEL + h*DKV + c) = lo;
                *(float2*)(C + ((size_t)b*SEQ + r1)*DMODEL + h*DKV + c) = hi;
            } else {
                *(float2*)(C + (size_t)r0 * N + c) = lo;
                *(float2*)(C + (size_t)r1 * N + c) = hi;
            }
        }
    }
}

// ---------------- row softmax over 1024, in place ----------------
__global__ __launch_bounds__(256) void softmax_rows(float* __restrict__ attn)
{
    __shared__ float sbuf[256];
    const size_t row = blockIdx.x;
    float* p = attn + row * 1024;
    const int tid = threadIdx.x;
    float4 v = *(const float4*)(p + tid*4);
    float m = fmaxf(fmaxf(v.x, v.y), fmaxf(v.z, v.w));
    sbuf[tid] = m; __syncthreads();
    for (int s = 128; s > 0; s >>= 1) {
        if (tid < s) sbuf[tid] = fmaxf(sbuf[tid], sbuf[tid+s]);
        __syncthreads();
    }
    m = sbuf[0]; __syncthreads();
    v.x = __expf(v.x - m); v.y = __expf(v.y - m);
    v.z = __expf(v.z - m); v.w = __expf(v.w - m);
    sbuf[tid] = v.x + v.y + v.z + v.w; __syncthreads();
    for (int s = 128; s > 0; s >>= 1) {
        if (tid < s) sbuf[tid] += sbuf[tid+s];
        __syncthreads();
    }
    const float inv = 1.f / sbuf[0];
    v.x *= inv; v.y *= inv; v.z *= inv; v.w *= inv;
    *(float4*)(p + tid*4) = v;
}

// ---------------- layernorm over last dim 1024 ----------------
__global__ __launch_bounds__(256) void layernorm_rows(
    const float* __restrict__ in, const float* __restrict__ g,
    const float* __restrict__ bta, float* __restrict__ out)
{
    __shared__ float s1[256], s2[256];
    const size_t row = blockIdx.x;
    const float* p = in + row * DMODEL;
    const int tid = threadIdx.x;
    float4 v = *(const float4*)(p + tid*4);
    s1[tid] = v.x + v.y + v.z + v.w;
    s2[tid] = v.x*v.x + v.y*v.y + v.z*v.z + v.w*v.w;
    __syncthreads();
    for (int st = 128; st > 0; st >>= 1) {
        if (tid < st) { s1[tid] += s1[tid+st]; s2[tid] += s2[tid+st]; }
        __syncthreads();
    }
    const float mu  = s1[0] * (1.f/DMODEL);
    const float var = s2[0] * (1.f/DMODEL) - mu*mu;
    const float rs  = rsqrtf(var + 1e-5f);
    float4 gv = *(const float4*)(g + tid*4);
    float4 bv = *(const float4*)(bta + tid*4);
    float4 o;
    o.x = (v.x - mu)*rs*gv.x + bv.x;
    o.y = (v.y - mu)*rs*gv.y + bv.y;
    o.z = (v.z - mu)*rs*gv.z + bv.z;
    o.w = (v.w - mu)*rs*gv.w + bv.w;
    *(float4*)(out + row*DMODEL + tid*4) = o;
}

// ---------------- launch ----------------
extern "C" void kernel_launch(void* const* d_in, const int* in_sizes, int n_in,
                              void* d_out, int out_size)
{
    const float* x    = (const float*)d_in[0];
    const unsigned char* mask = (const unsigned char*)d_in[1];
    const float* Wq = (const float*)d_in[2];  const float* bq = (const float*)d_in[3];
    const float* Wk = (const float*)d_in[4];  const float* bk = (const float*)d_in[5];
    const float* Wv = (const float*)d_in[6];  const float* bv = (const float*)d_in[7];
    const float* Wo = (const float*)d_in[8];  const float* bo = (const float*)d_in[9];
    const float* ln1g = (const float*)d_in[10]; const float* ln1b = (const float*)d_in[11];
    const float* W1 = (const float*)d_in[12]; const float* b1 = (const float*)d_in[13];
    const float* W2 = (const float*)d_in[14]; const float* b2 = (const float*)d_in[15];
    const float* ln2g = (const float*)d_in[16]; const float* ln2b = (const float*)d_in[17];

    float* out = (float*)d_out;
    float* ffn_out = out;                                    // [B,S,D]
    float* attn    = out + (size_t)MROWS * DMODEL;           // [B,H,S,S]

    float *qp, *kp, *vp, *ctxp, *tmpp, *aop, *hp;
    cudaGetSymbolAddress((void**)&qp,   g_q);
    cudaGetSymbolAddress((void**)&kp,   g_k);
    cudaGetSymbolAddress((void**)&vp,   g_v);
    cudaGetSymbolAddress((void**)&ctxp, g_ctx);
    cudaGetSymbolAddress((void**)&tmpp, g_tmp);
    cudaGetSymbolAddress((void**)&aop,  g_ao);
    cudaGetSymbolAddress((void**)&hp,   g_h);

    // QKV projections -> [B,H,S,Dk]
    gemm_tc2<128,1,false><<<dim3(8,64,1),256>>>(x, Wq, bq, nullptr, nullptr, qp, MROWS, DMODEL, DMODEL, 0,0,0);
    gemm_tc2<128,1,false><<<dim3(8,64,1),256>>>(x, Wk, bk, nullptr, nullptr, kp, MROWS, DMODEL, DMODEL, 0,0,0);
    gemm_tc2<128,1,false><<<dim3(8,64,1),256>>>(x, Wv, bv, nullptr, nullptr, vp, MROWS, DMODEL, DMODEL, 0,0,0);

    // scores: q @ k^T * 0.125 + mask -> attn, then softmax in place
    gemm_tc2<128,4,true><<<dim3(8,8,BH),256>>>(qp, kp, nullptr, nullptr, mask, attn,
                                               SEQ, SEQ, DKV,
                                               (long long)SEQ*DKV, (long long)SEQ*DKV, (long long)SEQ*SEQ);
    softmax_rows<<<BH * SEQ, 256>>>(attn);

    // ctx = attn @ v -> [B,S,H*Dv]
    gemm_tc2<64,5,false><<<dim3(1,8,BH),256>>>(attn, vp, nullptr, nullptr, nullptr, ctxp,
                                               SEQ, DKV, SEQ,
                                               (long long)SEQ*SEQ, (long long)SEQ*DKV, 0);

    // out proj + residual, LN1
    gemm_tc2<128,2,false><<<dim3(8,64,1),256>>>(ctxp, Wo, bo, x, nullptr, tmpp, MROWS, DMODEL, DMODEL, 0,0,0);
    layernorm_rows<<<MROWS, 256>>>(tmpp, ln1g, ln1b, aop);

    // FFN
    gemm_tc2<128,3,false><<<dim3(32,64,1),256>>>(aop, W1, b1, nullptr, nullptr, hp, MROWS, DFF, DMODEL, 0,0,0);
    gemm_tc2<128,2,false><<<dim3(8,64,1),256>>>(hp, W2, b2, aop, nullptr, tmpp, MROWS, DMODEL, DFF, 0,0,0);
    layernorm_rows<<<MROWS, 256>>>(tmpp, ln2g, ln2b, ffn_out);
}

// round 5
// speedup vs baseline: 1.7725x; 1.1125x over previous
#include <cuda_runtime.h>
#include <math.h>

#define DMODEL 1024
#define DFF    4096
#define NHEADS 16
#define DKV    64
#define BATCH  8
#define SEQ    1024
#define MROWS  (BATCH*SEQ)    // 8192
#define BH     (BATCH*NHEADS) // 128

// ---------------- scratch (no allocations allowed) ----------------
__device__ __align__(256) float g_q[BH*SEQ*DKV];       // [B,H,S,Dk] (tf32-rounded)
__device__ __align__(256) float g_k[BH*SEQ*DKV];
__device__ __align__(256) float g_v[BH*SEQ*DKV];
__device__ __align__(256) float g_ctx[MROWS*DMODEL];   // rounded
__device__ __align__(256) float g_tmp[MROWS*DMODEL];   // pre-LN buffer (fp32)
__device__ __align__(256) float g_ao[MROWS*DMODEL];    // LN1 out fp32 (residual)
__device__ __align__(256) float g_aor[MROWS*DMODEL];   // LN1 out rounded (FFN1 A)
__device__ __align__(256) float g_xr[MROWS*DMODEL];    // x rounded (QKV A)
__device__ __align__(256) float g_h[(size_t)MROWS*DFF];// FFN hidden (rounded)
__device__ __align__(256) float g_wqr[DMODEL*DMODEL];
__device__ __align__(256) float g_wkr[DMODEL*DMODEL];
__device__ __align__(256) float g_wvr[DMODEL*DMODEL];
__device__ __align__(256) float g_wor[DMODEL*DMODEL];
__device__ __align__(256) float g_w1r[DMODEL*DFF];
__device__ __align__(256) float g_w2r[DFF*DMODEL];

// ---------------- helpers ----------------
__device__ __forceinline__ unsigned f2tf(float x) {
    unsigned u;
    asm("cvt.rna.tf32.f32 %0, %1;" : "=r"(u) : "f"(x));
    return u;
}
__device__ __forceinline__ float f2tff(float x) { return __uint_as_float(f2tf(x)); }

__device__ __forceinline__ void mma_tf32(float* c, const unsigned* a, const unsigned* b) {
    asm volatile(
        "mma.sync.aligned.m16n8k8.row.col.f32.tf32.tf32.f32 "
        "{%0,%1,%2,%3},{%4,%5,%6,%7},{%8,%9},{%0,%1,%2,%3};"
        : "+f"(c[0]), "+f"(c[1]), "+f"(c[2]), "+f"(c[3])
        : "r"(a[0]), "r"(a[1]), "r"(a[2]), "r"(a[3]), "r"(b[0]), "r"(b[1]));
}

__device__ __forceinline__ unsigned sptr(const void* p) {
    return (unsigned)__cvta_generic_to_shared(p);
}
#define CP_ASYNC16(dst, src) \
    asm volatile("cp.async.cg.shared.global [%0], [%1], 16;" :: "r"(dst), "l"(src))
#define CP_COMMIT() asm volatile("cp.async.commit_group;")
#define CP_WAIT(n)  asm volatile("cp.async.wait_group %0;" :: "n"(n))

// ---------------- tf32 round-copy (inputs pre-rounded in gmem) ----------------
__global__ void round_tf(const float* __restrict__ in, float* __restrict__ out, int n4)
{
    int i = blockIdx.x * blockDim.x + threadIdx.x;
    if (i < n4) {
        float4 v = ((const float4*)in)[i];
        v.x = f2tff(v.x); v.y = f2tff(v.y); v.z = f2tff(v.z); v.w = f2tff(v.w);
        ((float4*)out)[i] = v;
    }
}

// =====================================================================
// cp.async pipelined tensor-core GEMM.  Block 128 x 128 x 16, S=4 stages.
// 8 warps (2M x 4N), warp tile 64 x 32 (4x4 m16n8k8 tf32 atoms).
// Inputs must already be tf32-rounded in gmem (raw bits fed to mma).
// modes: 1 qkv-remap(+bias,round), 2 +bias+resid, 3 relu(+bias,round),
//        4 scores(scale+mask)
// =====================================================================
template<int MODE, bool TRANSB>
__global__ void __launch_bounds__(256, 2) gemm_cp(
    const float* __restrict__ A, const float* __restrict__ B,
    const float* __restrict__ bias, const float* __restrict__ resid,
    const unsigned char* __restrict__ mask,
    float* __restrict__ C, int M, int N, int K,
    long long sA, long long sB, long long sC)
{
    constexpr int S  = 4;
    constexpr int AW = 128 * 20;                       // words / A stage
    constexpr int BW = TRANSB ? 128 * 20 : 16 * 132;   // words / B stage

    extern __shared__ float smp[];
    float* Asm = smp;
    float* Bsm = smp + S * AW;

    const int tid = threadIdx.x;
    const int bm = blockIdx.y, bn = blockIdx.x, bz = blockIdx.z;
    A += (long long)bz * sA;
    B += (long long)bz * sB;
    C += (long long)bz * sC;

    const int lane = tid & 31, wid = tid >> 5;
    const int warpM = wid >> 2, warpN = wid & 3;
    const int g = lane >> 2, t = lane & 3;

    // staging roles
    const int arow = tid >> 1, aoct = tid & 1;
    const float* Ag = A + (size_t)(bm * 128 + arow) * K + aoct * 8;
    const unsigned aD0 = sptr(Asm) + (arow * 20 + aoct * 8) * 4;

    const float* Bg;
    unsigned bD0;
    if (TRANSB) {
        Bg  = B + (size_t)(bn * 128 + arow) * K + aoct * 8;
        bD0 = sptr(Bsm) + (arow * 20 + aoct * 8) * 4;
    } else {
        const int bk = tid >> 4, bnn = (tid & 15) * 8;
        Bg  = B + (size_t)bk * N + bn * 128 + bnn;
        bD0 = sptr(Bsm) + (bk * 132 + bnn) * 4;
    }

    const int nch = K >> 4;

    auto load_chunk = [&](int ch) {
        const int st = ch & (S - 1);
        const float* ap = Ag + ch * 16;
        unsigned ad = aD0 + st * AW * 4;
        CP_ASYNC16(ad, ap);
        CP_ASYNC16(ad + 16, ap + 4);
        unsigned bd = bD0 + st * BW * 4;
        if (TRANSB) {
            const float* bp = Bg + ch * 16;
            CP_ASYNC16(bd, bp);
            CP_ASYNC16(bd + 16, bp + 4);
        } else {
            const float* bp = Bg + (size_t)ch * 16 * N;
            CP_ASYNC16(bd, bp);
            CP_ASYNC16(bd + 16, bp + 4);
        }
    };

    float acc[4][4][4];
    #pragma unroll
    for (int i = 0; i < 4; i++)
        #pragma unroll
        for (int j = 0; j < 4; j++)
            #pragma unroll
            for (int r = 0; r < 4; r++) acc[i][j][r] = 0.f;

    #pragma unroll
    for (int ch = 0; ch < S - 1; ch++) {
        if (ch < nch) load_chunk(ch);
        CP_COMMIT();
    }

    for (int ch = 0; ch < nch; ch++) {
        CP_WAIT(S - 2);
        __syncthreads();
        if (ch + S - 1 < nch) load_chunk(ch + S - 1);
        CP_COMMIT();

        const float* As = Asm + (ch & (S - 1)) * AW;
        const float* Bs = Bsm + (ch & (S - 1)) * BW;

        #pragma unroll
        for (int ks = 0; ks < 2; ks++) {
            const int kk = ks * 8;
            unsigned af[4][4], bfr[4][2];
            #pragma unroll
            for (int mt = 0; mt < 4; mt++) {
                const int m0 = warpM * 64 + mt * 16 + g;
                af[mt][0] = __float_as_uint(As[m0 * 20 + kk + t]);
                af[mt][1] = __float_as_uint(As[(m0 + 8) * 20 + kk + t]);
                af[mt][2] = __float_as_uint(As[m0 * 20 + kk + t + 4]);
                af[mt][3] = __float_as_uint(As[(m0 + 8) * 20 + kk + t + 4]);
            }
            #pragma unroll
            for (int nt = 0; nt < 4; nt++) {
                const int n0 = warpN * 32 + nt * 8 + g;
                if (TRANSB) {
                    bfr[nt][0] = __float_as_uint(Bs[n0 * 20 + kk + t]);
                    bfr[nt][1] = __float_as_uint(Bs[n0 * 20 + kk + t + 4]);
                } else {
                    bfr[nt][0] = __float_as_uint(Bs[(kk + t) * 132 + n0]);
                    bfr[nt][1] = __float_as_uint(Bs[(kk + t + 4) * 132 + n0]);
                }
            }
            #pragma unroll
            for (int mt = 0; mt < 4; mt++)
                #pragma unroll
                for (int nt = 0; nt < 4; nt++)
                    mma_tf32(acc[mt][nt], af[mt], bfr[nt]);
        }
    }

    // ---- epilogue ----
    #pragma unroll
    for (int mt = 0; mt < 4; mt++) {
        const int r0 = bm * 128 + warpM * 64 + mt * 16 + g;
        const int r1 = r0 + 8;
        #pragma unroll
        for (int nt = 0; nt < 4; nt++) {
            const int c = bn * 128 + warpN * 32 + nt * 8 + 2 * t;
            float2 lo = make_float2(acc[mt][nt][0], acc[mt][nt][1]);  // row r0
            float2 hi = make_float2(acc[mt][nt][2], acc[mt][nt][3]);  // row r1

            if (MODE == 1 || MODE == 2 || MODE == 3) {
                const float2 bv = *(const float2*)(bias + c);
                lo.x += bv.x; lo.y += bv.y; hi.x += bv.x; hi.y += bv.y;
            }
            if (MODE == 2) {
                const float2 q0 = *(const float2*)(resid + (size_t)r0 * N + c);
                const float2 q1 = *(const float2*)(resid + (size_t)r1 * N + c);
                lo.x += q0.x; lo.y += q0.y; hi.x += q1.x; hi.y += q1.y;
            }
            if (MODE == 3) {
                lo.x = f2tff(fmaxf(lo.x, 0.f)); lo.y = f2tff(fmaxf(lo.y, 0.f));
                hi.x = f2tff(fmaxf(hi.x, 0.f)); hi.y = f2tff(fmaxf(hi.y, 0.f));
            }

            if (MODE == 1) {
                lo.x = f2tff(lo.x); lo.y = f2tff(lo.y);
                hi.x = f2tff(hi.x); hi.y = f2tff(hi.y);
                const int h = c >> 6, d = c & 63;
                const int bb0 = r0 >> 10, s0 = r0 & 1023;
                const int bb1 = r1 >> 10, s1 = r1 & 1023;
                *(float2*)(C + (((size_t)(bb0*NHEADS + h))*SEQ + s0)*DKV + d) = lo;
                *(float2*)(C + (((size_t)(bb1*NHEADS + h))*SEQ + s1)*DKV + d) = hi;
            } else if (MODE == 4) {
                const unsigned char* mb = mask + (size_t)(bz >> 4) * SEQ * SEQ;
                lo.x *= 0.125f; lo.y *= 0.125f; hi.x *= 0.125f; hi.y *= 0.125f;
                if (mb[(size_t)r0*SEQ + c])     lo.x = -1e9f;
                if (mb[(size_t)r0*SEQ + c + 1]) lo.y = -1e9f;
                if (mb[(size_t)r1*SEQ + c])     hi.x = -1e9f;
                if (mb[(size_t)r1*SEQ + c + 1]) hi.y = -1e9f;
                *(float2*)(C + (size_t)r0 * N + c) = lo;
                *(float2*)(C + (size_t)r1 * N + c) = hi;
            } else {
                *(float2*)(C + (size_t)r0 * N + c) = lo;
                *(float2*)(C + (size_t)r1 * N + c) = hi;
            }
        }
    }
}

// =====================================================================
// Register-staged kernel for ctx (N=64): attn fp32 -> f2tf at staging.
// Epilogue rounds output (feeds Wo GEMM).
// =====================================================================
__device__ __forceinline__ unsigned a_off(int mtks, int lane, int slot) {
    unsigned b = ((unsigned)mtks << 9) + (lane << 4) + (slot << 2);
    return b ^ ((b >> 3) & 0x70);
}
__device__ __forceinline__ unsigned b_off(int ntks, int lane, int lohi) {
    unsigned b = ((unsigned)ntks << 8) + (lane << 3) + (lohi << 2);
    return b ^ ((b >> 5) & 0x70) ^ ((b >> 4) & 0x10);
}

__global__ void __launch_bounds__(256, 2) gemm_ctx(
    const float* __restrict__ A, const float* __restrict__ B,
    float* __restrict__ C, int K,
    long long sA, long long sB)
{
    constexpr int BN = 64, NT = BN / 32, BPC = BN / 16;
    constexpr int AW = 2048, BW = BN * 16;
    __shared__ __align__(16) unsigned Asm[2][AW];
    __shared__ __align__(16) unsigned Bsm[2][BW];

    const int tid = threadIdx.x;
    const int bm = blockIdx.y, bz = blockIdx.z;
    A += (long long)bz * sA;
    B += (long long)bz * sB;

    const int lane = tid & 31, wid = tid >> 5;
    const int warpM = wid >> 2, warpN = wid & 3;
    const int g = lane >> 2, t = lane & 3;

    const int arow = tid >> 1, aks = tid & 1;
    const float* Ag = A + (size_t)(bm * 128 + arow) * K + aks * 8;
    const int amtile = arow >> 4, ag = arow & 7, ahi = (arow >> 3) & 1;

    const int b_krow = tid >> 4, b_noff = (tid & 15) * BPC;
    const float* Bg = B + (size_t)b_krow * BN + b_noff;

    float fa[8], fb[BPC];
    float acc[4][NT][4];
    #pragma unroll
    for (int i = 0; i < 4; i++)
        #pragma unroll
        for (int j = 0; j < NT; j++)
            #pragma unroll
            for (int r = 0; r < 4; r++) acc[i][j][r] = 0.f;

    const int nch = K >> 4;

    auto fetch = [&](int ch) {
        const float* p = Ag + ch * 16;
        float4 u = *(const float4*)p, v = *(const float4*)(p + 4);
        fa[0]=u.x; fa[1]=u.y; fa[2]=u.z; fa[3]=u.w;
        fa[4]=v.x; fa[5]=v.y; fa[6]=v.z; fa[7]=v.w;
        const float* q = Bg + (size_t)ch * 16 * BN;
        float4 a = *(const float4*)q;
        fb[0]=a.x; fb[1]=a.y; fb[2]=a.z; fb[3]=a.w;
    };
    auto store_stage = [&](int st) {
        char* Ab = (char*)Asm[st];
        #pragma unroll
        for (int c = 0; c < 8; c++) {
            const int tt = c & 3, lohi = c >> 2;
            const int sl = ahi + 2 * lohi;
            *(unsigned*)(Ab + a_off(amtile * 2 + aks, ag * 4 + tt, sl)) = f2tf(fa[c]);
        }
        char* Bb = (char*)Bsm[st];
        const int ks = b_krow >> 3, tt = b_krow & 3, lohi = (b_krow >> 2) & 1;
        #pragma unroll
        for (int c = 0; c < BPC; c++) {
            const int n = b_noff + c;
            const int ntile = n >> 3, bg = n & 7;
            *(unsigned*)(Bb + b_off(ntile * 2 + ks, bg * 4 + tt, lohi)) = f2tf(fb[c]);
        }
    };

    fetch(0);
    store_stage(0);
    __syncthreads();

    for (int ch = 0; ch < nch; ch++) {
        const int cur = ch & 1, nxt = cur ^ 1;
        const bool more = (ch + 1 < nch);
        if (more) fetch(ch + 1);

        const char* Ac = (const char*)Asm[cur];
        const char* Bc = (const char*)Bsm[cur];
        #pragma unroll
        for (int ks = 0; ks < 2; ks++) {
            unsigned af[4][4], bfr[NT][2];
            #pragma unroll
            for (int mt = 0; mt < 4; mt++) {
                uint4 v = *(const uint4*)(Ac + a_off((warpM * 4 + mt) * 2 + ks, lane, 0));
                af[mt][0] = v.x; af[mt][1] = v.y; af[mt][2] = v.z; af[mt][3] = v.w;
            }
            #pragma unroll
            for (int nt = 0; nt < NT; nt++) {
                uint2 v = *(const uint2*)(Bc + b_off((warpN * NT + nt) * 2 + ks, lane, 0));
                bfr[nt][0] = v.x; bfr[nt][1] = v.y;
            }
            #pragma unroll
            for (int mt = 0; mt < 4; mt++)
                #pragma unroll
                for (int nt = 0; nt < NT; nt++)
                    mma_tf32(acc[mt][nt], af[mt], bfr[nt]);
        }
        if (more) store_stage(nxt);
        __syncthreads();
    }

    // epilogue: ctx remap [B,S,H*Dv], rounded
    const int b = bz >> 4, h = bz & 15;
    #pragma unroll
    for (int mt = 0; mt < 4; mt++) {
        const int r0 = bm * 128 + warpM * 64 + mt * 16 + g;
        const int r1 = r0 + 8;
        #pragma unroll
        for (int nt = 0; nt < NT; nt++) {
            const int c = warpN * (BN / 4) + nt * 8 + 2 * t;
            float2 lo = make_float2(f2tff(acc[mt][nt][0]), f2tff(acc[mt][nt][1]));
            float2 hi = make_float2(f2tff(acc[mt][nt][2]), f2tff(acc[mt][nt][3]));
            *(float2*)(C + ((size_t)b*SEQ + r0)*DMODEL + h*DKV + c) = lo;
            *(float2*)(C + ((size_t)b*SEQ + r1)*DMODEL + h*DKV + c) = hi;
        }
    }
}

// ---------------- row softmax over 1024, in place (shuffle reduce) ----------------
__global__ __launch_bounds__(256) void softmax_rows(float* __restrict__ attn)
{
    __shared__ float sw[8];
    const size_t row = blockIdx.x;
    float* p = attn + row * 1024;
    const int tid = threadIdx.x, lane = tid & 31, wid = tid >> 5;
    float4 v = *(const float4*)(p + tid*4);
    float m = fmaxf(fmaxf(v.x, v.y), fmaxf(v.z, v.w));
    #pragma unroll
    for (int o = 16; o; o >>= 1) m = fmaxf(m, __shfl_xor_sync(~0u, m, o));
    if (lane == 0) sw[wid] = m;
    __syncthreads();
    m = sw[0];
    #pragma unroll
    for (int i = 1; i < 8; i++) m = fmaxf(m, sw[i]);
    v.x = __expf(v.x - m); v.y = __expf(v.y - m);
    v.z = __expf(v.z - m); v.w = __expf(v.w - m);
    float s = v.x + v.y + v.z + v.w;
    #pragma unroll
    for (int o = 16; o; o >>= 1) s += __shfl_xor_sync(~0u, s, o);
    __syncthreads();            // protect sw reuse
    if (lane == 0) sw[wid] = s;
    __syncthreads();
    s = sw[0];
    #pragma unroll
    for (int i = 1; i < 8; i++) s += sw[i];
    const float inv = 1.f / s;
    v.x *= inv; v.y *= inv; v.z *= inv; v.w *= inv;
    *(float4*)(p + tid*4) = v;
}

// ---------------- layernorm over last dim 1024 (optional dual output) ----------------
template<bool DUAL>
__global__ void __launch_bounds__(256) layernorm_rows(
    const float* __restrict__ in, const float* __restrict__ g,
    const float* __restrict__ bta, float* __restrict__ out,
    float* __restrict__ out_r)
{
    __shared__ float s1w[8], s2w[8];
    const size_t row = blockIdx.x;
    const float* p = in + row * DMODEL;
    const int tid = threadIdx.x, lane = tid & 31, wid = tid >> 5;
    float4 v = *(const float4*)(p + tid*4);
    float s1 = v.x + v.y + v.z + v.w;
    float s2 = v.x*v.x + v.y*v.y + v.z*v.z + v.w*v.w;
    #pragma unroll
    for (int o = 16; o; o >>= 1) {
        s1 += __shfl_xor_sync(~0u, s1, o);
        s2 += __shfl_xor_sync(~0u, s2, o);
    }
    if (lane == 0) { s1w[wid] = s1; s2w[wid] = s2; }
    __syncthreads();
    s1 = s1w[0]; s2 = s2w[0];
    #pragma unroll
    for (int i = 1; i < 8; i++) { s1 += s1w[i]; s2 += s2w[i]; }
    const float mu  = s1 * (1.f/DMODEL);
    const float var = s2 * (1.f/DMODEL) - mu*mu;
    const float rs  = rsqrtf(var + 1e-5f);
    float4 gv = *(const float4*)(g + tid*4);
    float4 bv = *(const float4*)(bta + tid*4);
    float4 o;
    o.x = (v.x - mu)*rs*gv.x + bv.x;
    o.y = (v.y - mu)*rs*gv.y + bv.y;
    o.z = (v.z - mu)*rs*gv.z + bv.z;
    o.w = (v.w - mu)*rs*gv.w + bv.w;
    *(float4*)(out + row*DMODEL + tid*4) = o;
    if (DUAL) {
        float4 r;
        r.x = f2tff(o.x); r.y = f2tff(o.y); r.z = f2tff(o.z); r.w = f2tff(o.w);
        *(float4*)(out_r + row*DMODEL + tid*4) = r;
    }
}

// ---------------- launch ----------------
extern "C" void kernel_launch(void* const* d_in, const int* in_sizes, int n_in,
                              void* d_out, int out_size)
{
    const float* x    = (const float*)d_in[0];
    const unsigned char* mask = (const unsigned char*)d_in[1];
    const float* Wq = (const float*)d_in[2];  const float* bq = (const float*)d_in[3];
    const float* Wk = (const float*)d_in[4];  const float* bk = (const float*)d_in[5];
    const float* Wv = (const float*)d_in[6];  const float* bv = (const float*)d_in[7];
    const float* Wo = (const float*)d_in[8];  const float* bo = (const float*)d_in[9];
    const float* ln1g = (const float*)d_in[10]; const float* ln1b = (const float*)d_in[11];
    const float* W1 = (const float*)d_in[12]; const float* b1 = (const float*)d_in[13];
    const float* W2 = (const float*)d_in[14]; const float* b2 = (const float*)d_in[15];
    const float* ln2g = (const float*)d_in[16]; const float* ln2b = (const float*)d_in[17];

    float* out = (float*)d_out;
    float* ffn_out = out;                                    // [B,S,D]
    float* attn    = out + (size_t)MROWS * DMODEL;           // [B,H,S,S]

    float *qp, *kp, *vp, *ctxp, *tmpp, *aop, *aorp, *xrp, *hp;
    float *wqr, *wkr, *wvr, *wor, *w1r, *w2r;
    cudaGetSymbolAddress((void**)&qp,   g_q);
    cudaGetSymbolAddress((void**)&kp,   g_k);
    cudaGetSymbolAddress((void**)&vp,   g_v);
    cudaGetSymbolAddress((void**)&ctxp, g_ctx);
    cudaGetSymbolAddress((void**)&tmpp, g_tmp);
    cudaGetSymbolAddress((void**)&aop,  g_ao);
    cudaGetSymbolAddress((void**)&aorp, g_aor);
    cudaGetSymbolAddress((void**)&xrp,  g_xr);
    cudaGetSymbolAddress((void**)&hp,   g_h);
    cudaGetSymbolAddress((void**)&wqr,  g_wqr);
    cudaGetSymbolAddress((void**)&wkr,  g_wkr);
    cudaGetSymbolAddress((void**)&wvr,  g_wvr);
    cudaGetSymbolAddress((void**)&wor,  g_wor);
    cudaGetSymbolAddress((void**)&w1r,  g_w1r);
    cudaGetSymbolAddress((void**)&w2r,  g_w2r);

    // dyn smem sizes for gemm_cp
    const int SMD = 4 * (128*20 + 16*132) * 4;   // dense: 74,688 B
    const int SMT = 4 * (128*20 + 128*20) * 4;   // trans: 81,920 B
    cudaFuncSetAttribute(gemm_cp<1,false>, cudaFuncAttributeMaxDynamicSharedMemorySize, SMD);
    cudaFuncSetAttribute(gemm_cp<2,false>, cudaFuncAttributeMaxDynamicSharedMemorySize, SMD);
    cudaFuncSetAttribute(gemm_cp<3,false>, cudaFuncAttributeMaxDynamicSharedMemorySize, SMD);
    cudaFuncSetAttribute(gemm_cp<4,true>,  cudaFuncAttributeMaxDynamicSharedMemorySize, SMT);

    // ---- pre-round inputs to tf32 in gmem ----
    auto rnd = [&](const float* src, float* dst, int n) {
        int n4 = n / 4;
        round_tf<<<(n4 + 255)/256, 256>>>(src, dst, n4);
    };
    rnd(x,  xrp, MROWS*DMODEL);
    rnd(Wq, wqr, DMODEL*DMODEL);
    rnd(Wk, wkr, DMODEL*DMODEL);
    rnd(Wv, wvr, DMODEL*DMODEL);
    rnd(Wo, wor, DMODEL*DMODEL);
    rnd(W1, w1r, DMODEL*DFF);
    rnd(W2, w2r, DFF*DMODEL);

    // QKV projections -> [B,H,S,Dk] (rounded)
    gemm_cp<1,false><<<dim3(8,64,1),256,SMD>>>(xrp, wqr, bq, nullptr, nullptr, qp, MROWS, DMODEL, DMODEL, 0,0,0);
    gemm_cp<1,false><<<dim3(8,64,1),256,SMD>>>(xrp, wkr, bk, nullptr, nullptr, kp, MROWS, DMODEL, DMODEL, 0,0,0);
    gemm_cp<1,false><<<dim3(8,64,1),256,SMD>>>(xrp, wvr, bv, nullptr, nullptr, vp, MROWS, DMODEL, DMODEL, 0,0,0);

    // scores: q @ k^T * 0.125 + mask -> attn (fp32), softmax in place
    gemm_cp<4,true><<<dim3(8,8,BH),256,SMT>>>(qp, kp, nullptr, nullptr, mask, attn,
                                              SEQ, SEQ, DKV,
                                              (long long)SEQ*DKV, (long long)SEQ*DKV, (long long)SEQ*SEQ);
    softmax_rows<<<BH * SEQ, 256>>>(attn);

    // ctx = attn @ v -> [B,S,H*Dv] (rounded)
    gemm_ctx<<<dim3(1,8,BH),256>>>(attn, vp, ctxp, SEQ,
                                   (long long)SEQ*SEQ, (long long)SEQ*DKV);

    // out proj + residual (raw x), LN1 (dual: fp32 + rounded)
    gemm_cp<2,false><<<dim3(8,64,1),256,SMD>>>(ctxp, wor, bo, x, nullptr, tmpp, MROWS, DMODEL, DMODEL, 0,0,0);
    layernorm_rows<true><<<MROWS, 256>>>(tmpp, ln1g, ln1b, aop, aorp);

    // FFN
    gemm_cp<3,false><<<dim3(32,64,1),256,SMD>>>(aorp, w1r, b1, nullptr, nullptr, hp, MROWS, DFF, DMODEL, 0,0,0);
    gemm_cp<2,false><<<dim3(8,64,1),256,SMD>>>(hp, w2r, b2, aop, nullptr, tmpp, MROWS, DMODEL, DFF, 0,0,0);
    layernorm_rows<false><<<MROWS, 256>>>(tmpp, ln2g, ln2b, ffn_out, nullptr);
}